// round 6
// baseline (speedup 1.0000x reference)
#include <cuda_runtime.h>
#include <cuda_bf16.h>

#define Bsz 8
#define Ssz 1024
#define Esz 768
#define Hsz 12
#define Dsz 64
#define Msz (Bsz*Ssz)   // 8192

// ---------------- scratch (device globals; no allocation) ----------------
__device__ float g_q[Bsz*Hsz*Ssz*Dsz];     // [B,H,S,D]
__device__ float g_k[Bsz*Hsz*Ssz*Dsz];
__device__ float g_v[Bsz*Hsz*Ssz*Dsz];
__device__ float g_attn[Bsz*Ssz*Esz];      // [B,S,E] concat-heads

// ---------------- helpers ----------------
__device__ __forceinline__ unsigned f2tf(float f) {
    unsigned u;
    asm("cvt.rna.tf32.f32 %0, %1;" : "=r"(u) : "f"(f));
    return u;
}
__device__ __forceinline__ void mma_tf32(float* c, const unsigned* a, unsigned b0, unsigned b1) {
    asm volatile(
        "mma.sync.aligned.m16n8k8.row.col.f32.tf32.tf32.f32 "
        "{%0,%1,%2,%3}, {%4,%5,%6,%7}, {%8,%9}, {%0,%1,%2,%3};"
        : "+f"(c[0]), "+f"(c[1]), "+f"(c[2]), "+f"(c[3])
        : "r"(a[0]), "r"(a[1]), "r"(a[2]), "r"(a[3]), "r"(b0), "r"(b1));
}
__device__ __forceinline__ void ldsm_x4(unsigned& r0, unsigned& r1, unsigned& r2, unsigned& r3,
                                        unsigned saddr) {
    asm volatile("ldmatrix.sync.aligned.m8n8.x4.shared.b16 {%0,%1,%2,%3}, [%4];"
        : "=r"(r0), "=r"(r1), "=r"(r2), "=r"(r3) : "r"(saddr));
}

// GEMM tile: block 128x128, Kc=16, 8 warps (2m x 4n), warp 64x32
#define AST 20      // A smem stride words ([m][k])
#define BKST 20     // B smem stride words ([n][k]) - transposed, LDSM-ready

// ============================================================================
// QKV projection, tf32 MMA, all fragments via ldmatrix.
// grid (Hsz/2, Msz/128, 3).
// ============================================================================
__global__ __launch_bounds__(256, 2) void qkv_mma(
    const float* __restrict__ X,
    const float* __restrict__ Wq, const float* __restrict__ bq,
    const float* __restrict__ Wk, const float* __restrict__ bk,
    const float* __restrict__ Wv, const float* __restrict__ bv)
{
    const int which = blockIdx.z;
    const float* W    = (which == 0) ? Wq : (which == 1 ? Wk : Wv);
    const float* bias = (which == 0) ? bq : (which == 1 ? bk : bv);
    float* OUT        = (which == 0) ? g_q : (which == 1 ? g_k : g_v);

    const int h0 = blockIdx.x * 2;
    const int m0 = blockIdx.y * 128;

    __shared__ unsigned As[2][128 * AST];  // 20.5 KB
    __shared__ unsigned Bs[2][128 * BKST]; // 20.5 KB

    const int t    = threadIdx.x;
    const int warp = t >> 5;
    const int lane = t & 31;
    const int g    = lane >> 2;
    const int tg   = lane & 3;
    const int wm   = (warp & 1) * 64;
    const int wn   = (warp >> 1) * 32;

    const unsigned a_lane = (((lane >> 3) & 1) * 8 + (lane & 7)) * AST + (lane >> 4) * 4;
    const unsigned b_lane = (lane & 7) * BKST + (lane >> 3) * 4;
    unsigned as_base0 = (unsigned)__cvta_generic_to_shared(&As[0][0]);
    unsigned as_base1 = (unsigned)__cvta_generic_to_shared(&As[1][0]);
    unsigned bs_base0 = (unsigned)__cvta_generic_to_shared(&Bs[0][0]);
    unsigned bs_base1 = (unsigned)__cvta_generic_to_shared(&Bs[1][0]);

    // A global mapping
    const int ar0 = t >> 2, ac = (t & 3) << 2;
    const float* Aptr = X + (m0 + ar0) * Esz + ac;
    // B global mapping: column gather. n = t&127, k-half = t>>7
    const int bn_ = t & 127;
    const int bkh = (t >> 7) << 3;         // 0 or 8
    const int bhead = h0 + (bn_ >> 6), bd = bn_ & 63;
    const float* Bcol = W + bhead * (Esz * Dsz) + bd;

    // prologue
    float4 pa0 = *(const float4*)(Aptr);
    float4 pa1 = *(const float4*)(Aptr + 64 * Esz);
    float pbv[8];
    #pragma unroll
    for (int j = 0; j < 8; j++) pbv[j] = Bcol[(bkh + j) * Dsz];
    {
        uint4 u;
        u.x = f2tf(pa0.x); u.y = f2tf(pa0.y); u.z = f2tf(pa0.z); u.w = f2tf(pa0.w);
        *(uint4*)&As[0][ar0 * AST + ac] = u;
        u.x = f2tf(pa1.x); u.y = f2tf(pa1.y); u.z = f2tf(pa1.z); u.w = f2tf(pa1.w);
        *(uint4*)&As[0][(ar0 + 64) * AST + ac] = u;
        u.x = f2tf(pbv[0]); u.y = f2tf(pbv[1]); u.z = f2tf(pbv[2]); u.w = f2tf(pbv[3]);
        *(uint4*)&Bs[0][bn_ * BKST + bkh] = u;
        u.x = f2tf(pbv[4]); u.y = f2tf(pbv[5]); u.z = f2tf(pbv[6]); u.w = f2tf(pbv[7]);
        *(uint4*)&Bs[0][bn_ * BKST + bkh + 4] = u;
    }
    __syncthreads();

    float acc[4][4][4];
    #pragma unroll
    for (int mi = 0; mi < 4; mi++)
        #pragma unroll
        for (int ni = 0; ni < 4; ni++)
            #pragma unroll
            for (int j = 0; j < 4; j++) acc[mi][ni][j] = 0.f;

    for (int k0 = 0; k0 < Esz; k0 += 16) {
        const int buf = (k0 >> 4) & 1;
        const unsigned as_base = buf ? as_base1 : as_base0;
        const unsigned bs_base = buf ? bs_base1 : bs_base0;
        const bool more = (k0 + 16) < Esz;
        if (more) {
            pa0 = *(const float4*)(Aptr + k0 + 16);
            pa1 = *(const float4*)(Aptr + 64 * Esz + k0 + 16);
            #pragma unroll
            for (int j = 0; j < 8; j++) pbv[j] = Bcol[(k0 + 16 + bkh + j) * Dsz];
        }
        // B fragments for the whole chunk (both k-steps)
        unsigned bf[4][4];
        #pragma unroll
        for (int ni = 0; ni < 4; ni++) {
            unsigned addr = bs_base + 4 * ((wn + ni * 8) * BKST + b_lane);
            ldsm_x4(bf[ni][0], bf[ni][1], bf[ni][2], bf[ni][3], addr);
        }
        #pragma unroll
        for (int ks = 0; ks < 2; ks++) {
            unsigned a[4][4];
            #pragma unroll
            for (int mi = 0; mi < 4; mi++) {
                unsigned addr = as_base + 4 * ((wm + mi * 16) * AST + ks * 8 + a_lane);
                ldsm_x4(a[mi][0], a[mi][1], a[mi][2], a[mi][3], addr);
            }
            #pragma unroll
            for (int ni = 0; ni < 4; ni++)
                #pragma unroll
                for (int mi = 0; mi < 4; mi++)
                    mma_tf32(acc[mi][ni], a[mi], bf[ni][2 * ks], bf[ni][2 * ks + 1]);
        }
        if (more) {
            const int nb = buf ^ 1;
            uint4 u;
            u.x = f2tf(pa0.x); u.y = f2tf(pa0.y); u.z = f2tf(pa0.z); u.w = f2tf(pa0.w);
            *(uint4*)&As[nb][ar0 * AST + ac] = u;
            u.x = f2tf(pa1.x); u.y = f2tf(pa1.y); u.z = f2tf(pa1.z); u.w = f2tf(pa1.w);
            *(uint4*)&As[nb][(ar0 + 64) * AST + ac] = u;
            u.x = f2tf(pbv[0]); u.y = f2tf(pbv[1]); u.z = f2tf(pbv[2]); u.w = f2tf(pbv[3]);
            *(uint4*)&Bs[nb][bn_ * BKST + bkh] = u;
            u.x = f2tf(pbv[4]); u.y = f2tf(pbv[5]); u.z = f2tf(pbv[6]); u.w = f2tf(pbv[7]);
            *(uint4*)&Bs[nb][bn_ * BKST + bkh + 4] = u;
        }
        __syncthreads();
    }

    // epilogue: bias + write [B,H,S,D]
    #pragma unroll
    for (int mi = 0; mi < 4; mi++) {
        const int row_lo = m0 + wm + mi * 16 + g;
        const int row_hi = row_lo + 8;
        const int blo = row_lo >> 10, slo = row_lo & 1023;
        const int bhi = row_hi >> 10, shi = row_hi & 1023;
        #pragma unroll
        for (int ni = 0; ni < 4; ni++) {
            const int col  = wn + ni * 8 + 2 * tg;
            const int head = h0 + (col >> 6);
            const int d    = col & 63;
            float2 bb = *(const float2*)(bias + head * Dsz + d);
            float* olo = OUT + (((blo * Hsz + head) << 10) + slo) * Dsz + d;
            float* ohi = OUT + (((bhi * Hsz + head) << 10) + shi) * Dsz + d;
            float2 wlo, whi;
            wlo.x = acc[mi][ni][0] + bb.x; wlo.y = acc[mi][ni][1] + bb.y;
            whi.x = acc[mi][ni][2] + bb.x; whi.y = acc[mi][ni][3] + bb.y;
            *(float2*)olo = wlo;
            *(float2*)ohi = whi;
        }
    }
}

// ============================================================================
// Output projection: same structure, B = Wo[768,768]. grid (6, 64).
// ============================================================================
__global__ __launch_bounds__(256, 2) void oproj_mma(
    const float* __restrict__ Wo, const float* __restrict__ bo,
    float* __restrict__ out)
{
    const int n0 = blockIdx.x * 128;
    const int m0 = blockIdx.y * 128;

    __shared__ unsigned As[2][128 * AST];
    __shared__ unsigned Bs[2][128 * BKST];

    const int t    = threadIdx.x;
    const int warp = t >> 5;
    const int lane = t & 31;
    const int g    = lane >> 2;
    const int tg   = lane & 3;
    const int wm   = (warp & 1) * 64;
    const int wn   = (warp >> 1) * 32;

    const unsigned a_lane = (((lane >> 3) & 1) * 8 + (lane & 7)) * AST + (lane >> 4) * 4;
    const unsigned b_lane = (lane & 7) * BKST + (lane >> 3) * 4;
    unsigned as_base0 = (unsigned)__cvta_generic_to_shared(&As[0][0]);
    unsigned as_base1 = (unsigned)__cvta_generic_to_shared(&As[1][0]);
    unsigned bs_base0 = (unsigned)__cvta_generic_to_shared(&Bs[0][0]);
    unsigned bs_base1 = (unsigned)__cvta_generic_to_shared(&Bs[1][0]);

    const int ar0 = t >> 2, ac = (t & 3) << 2;
    const float* Aptr = g_attn + (m0 + ar0) * Esz + ac;
    const int bn_ = t & 127;
    const int bkh = (t >> 7) << 3;
    const float* Bcol = Wo + n0 + bn_;

    float4 pa0 = *(const float4*)(Aptr);
    float4 pa1 = *(const float4*)(Aptr + 64 * Esz);
    float pbv[8];
    #pragma unroll
    for (int j = 0; j < 8; j++) pbv[j] = Bcol[(bkh + j) * Esz];
    {
        uint4 u;
        u.x = f2tf(pa0.x); u.y = f2tf(pa0.y); u.z = f2tf(pa0.z); u.w = f2tf(pa0.w);
        *(uint4*)&As[0][ar0 * AST + ac] = u;
        u.x = f2tf(pa1.x); u.y = f2tf(pa1.y); u.z = f2tf(pa1.z); u.w = f2tf(pa1.w);
        *(uint4*)&As[0][(ar0 + 64) * AST + ac] = u;
        u.x = f2tf(pbv[0]); u.y = f2tf(pbv[1]); u.z = f2tf(pbv[2]); u.w = f2tf(pbv[3]);
        *(uint4*)&Bs[0][bn_ * BKST + bkh] = u;
        u.x = f2tf(pbv[4]); u.y = f2tf(pbv[5]); u.z = f2tf(pbv[6]); u.w = f2tf(pbv[7]);
        *(uint4*)&Bs[0][bn_ * BKST + bkh + 4] = u;
    }
    __syncthreads();

    float acc[4][4][4];
    #pragma unroll
    for (int mi = 0; mi < 4; mi++)
        #pragma unroll
        for (int ni = 0; ni < 4; ni++)
            #pragma unroll
            for (int j = 0; j < 4; j++) acc[mi][ni][j] = 0.f;

    for (int k0 = 0; k0 < Esz; k0 += 16) {
        const int buf = (k0 >> 4) & 1;
        const unsigned as_base = buf ? as_base1 : as_base0;
        const unsigned bs_base = buf ? bs_base1 : bs_base0;
        const bool more = (k0 + 16) < Esz;
        if (more) {
            pa0 = *(const float4*)(Aptr + k0 + 16);
            pa1 = *(const float4*)(Aptr + 64 * Esz + k0 + 16);
            #pragma unroll
            for (int j = 0; j < 8; j++) pbv[j] = Bcol[(k0 + 16 + bkh + j) * Esz];
        }
        unsigned bf[4][4];
        #pragma unroll
        for (int ni = 0; ni < 4; ni++) {
            unsigned addr = bs_base + 4 * ((wn + ni * 8) * BKST + b_lane);
            ldsm_x4(bf[ni][0], bf[ni][1], bf[ni][2], bf[ni][3], addr);
        }
        #pragma unroll
        for (int ks = 0; ks < 2; ks++) {
            unsigned a[4][4];
            #pragma unroll
            for (int mi = 0; mi < 4; mi++) {
                unsigned addr = as_base + 4 * ((wm + mi * 16) * AST + ks * 8 + a_lane);
                ldsm_x4(a[mi][0], a[mi][1], a[mi][2], a[mi][3], addr);
            }
            #pragma unroll
            for (int ni = 0; ni < 4; ni++)
                #pragma unroll
                for (int mi = 0; mi < 4; mi++)
                    mma_tf32(acc[mi][ni], a[mi], bf[ni][2 * ks], bf[ni][2 * ks + 1]);
        }
        if (more) {
            const int nb = buf ^ 1;
            uint4 u;
            u.x = f2tf(pa0.x); u.y = f2tf(pa0.y); u.z = f2tf(pa0.z); u.w = f2tf(pa0.w);
            *(uint4*)&As[nb][ar0 * AST + ac] = u;
            u.x = f2tf(pa1.x); u.y = f2tf(pa1.y); u.z = f2tf(pa1.z); u.w = f2tf(pa1.w);
            *(uint4*)&As[nb][(ar0 + 64) * AST + ac] = u;
            u.x = f2tf(pbv[0]); u.y = f2tf(pbv[1]); u.z = f2tf(pbv[2]); u.w = f2tf(pbv[3]);
            *(uint4*)&Bs[nb][bn_ * BKST + bkh] = u;
            u.x = f2tf(pbv[4]); u.y = f2tf(pbv[5]); u.z = f2tf(pbv[6]); u.w = f2tf(pbv[7]);
            *(uint4*)&Bs[nb][bn_ * BKST + bkh + 4] = u;
        }
        __syncthreads();
    }

    #pragma unroll
    for (int mi = 0; mi < 4; mi++) {
        const int row_lo = m0 + wm + mi * 16 + g;
        float* olo = out + row_lo * Esz + n0;
        float* ohi = out + (row_lo + 8) * Esz + n0;
        #pragma unroll
        for (int ni = 0; ni < 4; ni++) {
            const int col = wn + ni * 8 + 2 * tg;
            float2 bb = *(const float2*)(bo + n0 + col);
            float2 wlo, whi;
            wlo.x = acc[mi][ni][0] + bb.x; wlo.y = acc[mi][ni][1] + bb.y;
            whi.x = acc[mi][ni][2] + bb.x; whi.y = acc[mi][ni][3] + bb.y;
            *(float2*)(olo + col) = wlo;
            *(float2*)(ohi + col) = whi;
        }
    }
}

// ============================================================================
// Flash attention (tf32 mma) — K, P AND V fragments via ldmatrix.
// Vsm stored transposed [d][s] with XOR-group swizzle, stride 64.
// ============================================================================
#define KST 68

__global__ __launch_bounds__(128) void attn_kernel()
{
    __shared__ unsigned Ksm[64 * KST];     // K tile [n][k] -> reused as P [m][k]
    __shared__ unsigned Vsm[64 * 64];      // V^T tile [d][s], swizzled

    const int bh = blockIdx.y;
    const int b = bh / Hsz, h = bh % Hsz;
    const int tid  = threadIdx.x;
    const int warp = tid >> 5;
    const int lane = tid & 31;
    const int g  = lane >> 2;
    const int tg = lane & 3;
    const int r0 = warp * 16;

    const unsigned ks_base = (unsigned)__cvta_generic_to_shared(Ksm);
    const unsigned vs_base = (unsigned)__cvta_generic_to_shared(Vsm);
    const unsigned kf_lane = (lane & 7) * KST + (lane >> 3) * 4;
    const unsigned pf_lane = (((lane >> 3) & 1) * 8 + (lane & 7)) * KST + (lane >> 4) * 4;

    // V transposed-store mapping: thread owns column d, 32 s-values
    const int vd = tid & 63;
    const int vs0 = (tid >> 6) * 32;

    // ---- stage Q (scaled, tf32) into Ksm, extract A-frags ----
    {
        const float4* Qg = (const float4*)(g_q + (bh * Ssz + blockIdx.x * 64) * Dsz);
        #pragma unroll
        for (int i = 0; i < 8; i++) {
            int idx = i * 128 + tid;
            int row = idx >> 4, c = (idx & 15) << 2;
            float4 qv = Qg[idx];
            uint4 u;
            u.x = f2tf(qv.x * 0.125f);
            u.y = f2tf(qv.y * 0.125f);
            u.z = f2tf(qv.z * 0.125f);
            u.w = f2tf(qv.w * 0.125f);
            *(uint4*)&Ksm[row * KST + c] = u;
        }
    }
    __syncthreads();

    unsigned qa[8][4];
    #pragma unroll
    for (int kk = 0; kk < 8; kk++) {
        unsigned addr = ks_base + 4 * (r0 * KST + kk * 8 + pf_lane);
        ldsm_x4(qa[kk][0], qa[kk][1], qa[kk][2], qa[kk][3], addr);
    }
    __syncthreads();

    float o[8][4];
    #pragma unroll
    for (int nf = 0; nf < 8; nf++)
        #pragma unroll
        for (int j = 0; j < 4; j++) o[nf][j] = 0.f;
    float m_lo = -1e30f, m_hi = -1e30f, l_lo = 0.f, l_hi = 0.f;

    const float4* Kg0 = (const float4*)(g_k + bh * (Ssz * Dsz));
    const float*  Vg0 = g_v + bh * (Ssz * Dsz);

    for (int kb = 0; kb < Ssz / 64; kb++) {
        // ---- K tile: row-major tf32 ----
        const float4* Kg = Kg0 + kb * 1024;
        #pragma unroll
        for (int i = 0; i < 8; i++) {
            int idx = i * 128 + tid;
            int row = idx >> 4, c = (idx & 15) << 2;
            float4 kv = Kg[idx];
            uint4 uk;
            uk.x = f2tf(kv.x); uk.y = f2tf(kv.y); uk.z = f2tf(kv.z); uk.w = f2tf(kv.w);
            *(uint4*)&Ksm[row * KST + c] = uk;
        }
        // ---- V tile: transposed [d][s], swizzled groups ----
        {
            const float* Vt = Vg0 + kb * 64 * Dsz;
            #pragma unroll
            for (int sg = 0; sg < 8; sg++) {
                int s = vs0 + sg * 4;
                uint4 u;
                u.x = f2tf(Vt[(s + 0) * Dsz + vd]);
                u.y = f2tf(Vt[(s + 1) * Dsz + vd]);
                u.z = f2tf(Vt[(s + 2) * Dsz + vd]);
                u.w = f2tf(Vt[(s + 3) * Dsz + vd]);
                int grp = (s >> 2) ^ (vd & 7);
                *(uint4*)&Vsm[vd * 64 + grp * 4] = u;
            }
        }
        __syncthreads();

        // ---- S = Q K^T ----
        float s[8][4];
        #pragma unroll
        for (int nf = 0; nf < 8; nf++)
            #pragma unroll
            for (int j = 0; j < 4; j++) s[nf][j] = 0.f;

        #pragma unroll
        for (int nf = 0; nf < 8; nf++) {
            #pragma unroll
            for (int p = 0; p < 4; p++) {
                unsigned kb0, kb1, kb2, kb3;
                unsigned addr = ks_base + 4 * ((nf * 8) * KST + p * 16 + kf_lane);
                ldsm_x4(kb0, kb1, kb2, kb3, addr);
                mma_tf32(s[nf], qa[2 * p],     kb0, kb1);
                mma_tf32(s[nf], qa[2 * p + 1], kb2, kb3);
            }
        }
        __syncthreads();

        // ---- online softmax ----
        float tmax_lo = -1e30f, tmax_hi = -1e30f;
        #pragma unroll
        for (int nf = 0; nf < 8; nf++) {
            tmax_lo = fmaxf(tmax_lo, fmaxf(s[nf][0], s[nf][1]));
            tmax_hi = fmaxf(tmax_hi, fmaxf(s[nf][2], s[nf][3]));
        }
        tmax_lo = fmaxf(tmax_lo, __shfl_xor_sync(0xffffffffu, tmax_lo, 1));
        tmax_lo = fmaxf(tmax_lo, __shfl_xor_sync(0xffffffffu, tmax_lo, 2));
        tmax_hi = fmaxf(tmax_hi, __shfl_xor_sync(0xffffffffu, tmax_hi, 1));
        tmax_hi = fmaxf(tmax_hi, __shfl_xor_sync(0xffffffffu, tmax_hi, 2));

        float mn_lo = fmaxf(m_lo, tmax_lo);
        float mn_hi = fmaxf(m_hi, tmax_hi);
        float a_lo = __expf(m_lo - mn_lo);
        float a_hi = __expf(m_hi - mn_hi);

        float sum_lo = 0.f, sum_hi = 0.f;
        #pragma unroll
        for (int nf = 0; nf < 8; nf++) {
            float p0 = __expf(s[nf][0] - mn_lo);
            float p1 = __expf(s[nf][1] - mn_lo);
            float p2 = __expf(s[nf][2] - mn_hi);
            float p3 = __expf(s[nf][3] - mn_hi);
            sum_lo += p0 + p1;
            sum_hi += p2 + p3;
            uint2 plo, phi;
            plo.x = f2tf(p0); plo.y = f2tf(p1);
            phi.x = f2tf(p2); phi.y = f2tf(p3);
            *(uint2*)&Ksm[(r0 + g) * KST + nf * 8 + 2 * tg]     = plo;
            *(uint2*)&Ksm[(r0 + g + 8) * KST + nf * 8 + 2 * tg] = phi;
            o[nf][0] *= a_lo; o[nf][1] *= a_lo;
            o[nf][2] *= a_hi; o[nf][3] *= a_hi;
        }
        sum_lo += __shfl_xor_sync(0xffffffffu, sum_lo, 1);
        sum_lo += __shfl_xor_sync(0xffffffffu, sum_lo, 2);
        sum_hi += __shfl_xor_sync(0xffffffffu, sum_hi, 1);
        sum_hi += __shfl_xor_sync(0xffffffffu, sum_hi, 2);
        l_lo = l_lo * a_lo + sum_lo;
        l_hi = l_hi * a_hi + sum_hi;
        m_lo = mn_lo; m_hi = mn_hi;
        __syncwarp();                      // P visible within warp

        // ---- O += P V : P and V frags via ldmatrix ----
        #pragma unroll
        for (int p = 0; p < 4; p++) {
            unsigned paA[4], paB[4];
            unsigned addrA = ks_base + 4 * (r0 * KST + (2 * p) * 8 + pf_lane);
            unsigned addrB = ks_base + 4 * (r0 * KST + (2 * p + 1) * 8 + pf_lane);
            ldsm_x4(paA[0], paA[1], paA[2], paA[3], addrA);
            ldsm_x4(paB[0], paB[1], paB[2], paB[3], addrB);
            #pragma unroll
            for (int nf = 0; nf < 8; nf++) {
                // V frag rows d = nf*8+(lane&7); swizzled group = (p*4+(lane>>3)) ^ (lane&7)
                unsigned grp = (unsigned)((p * 4 + (lane >> 3)) ^ (lane & 7));
                unsigned addr = vs_base + 4 * ((nf * 8 + (lane & 7)) * 64 + grp * 4);
                unsigned v0, v1, v2, v3;
                ldsm_x4(v0, v1, v2, v3, addr);
                mma_tf32(o[nf], paA, v0, v1);
                mma_tf32(o[nf], paB, v2, v3);
            }
        }
        __syncthreads();
    }

    float inv_lo = 1.f / l_lo;
    float inv_hi = 1.f / l_hi;
    const int qrow_lo = blockIdx.x * 64 + r0 + g;
    float* out_lo = g_attn + (b * Ssz + qrow_lo) * Esz + h * Dsz;
    float* out_hi = out_lo + 8 * Esz;
    #pragma unroll
    for (int nf = 0; nf < 8; nf++) {
        int col = nf * 8 + 2 * tg;
        float2 wlo, whi;
        wlo.x = o[nf][0] * inv_lo; wlo.y = o[nf][1] * inv_lo;
        whi.x = o[nf][2] * inv_hi; whi.y = o[nf][3] * inv_hi;
        *(float2*)(out_lo + col) = wlo;
        *(float2*)(out_hi + col) = whi;
    }
}

// ---------------- launch ----------------
extern "C" void kernel_launch(void* const* d_in, const int* in_sizes, int n_in,
                              void* d_out, int out_size)
{
    const float* X  = (const float*)d_in[0];
    const float* Wq = (const float*)d_in[1];
    const float* bq = (const float*)d_in[2];
    const float* Wk = (const float*)d_in[3];
    const float* bk = (const float*)d_in[4];
    const float* Wv = (const float*)d_in[5];
    const float* bv = (const float*)d_in[6];
    const float* Wo = (const float*)d_in[7];
    const float* bo = (const float*)d_in[8];
    float* out = (float*)d_out;

    dim3 g1(Hsz / 2, Msz / 128, 3);        // (6, 64, 3)
    qkv_mma<<<g1, 256>>>(X, Wq, bq, Wk, bk, Wv, bv);

    dim3 g2(Ssz / 64, Bsz * Hsz);          // (16, 96)
    attn_kernel<<<g2, 128>>>();

    dim3 g3(Esz / 128, Msz / 128);         // (6, 64)
    oproj_mma<<<g3, 256>>>(Wo, bo, out);
}